// round 4
// baseline (speedup 1.0000x reference)
#include <cuda_runtime.h>

#define NN    4096
#define BB    256
#define VOC   200
#define TT    128
#define GRID  740
#define THR   128

// ---------------- scratch (device globals; no allocation) ----------------
static __device__ float g_hf[(size_t)NN * BB * 32];      // node states [node][b][feature]
static __device__ float2 g_p2[4 * BB * 16];              // root partials [cstride][b][jj]
static __device__ float g_Wl[32 * 32];
static __device__ float g_bl[32];
static __device__ float g_Pa[VOC * 32];
static __device__ float g_Pb[VOC * 32];
static __device__ float g_La[VOC * 32];
static __device__ float g_Lb[VOC * 32];
static __device__ float g_F[BB * 32];
static __device__ float g_Lt[(size_t)BB * TT * 32];
static __device__ float g_v[32];
static __device__ float g_s;
static __device__ int   g_cnt[NN];
static __device__ int   g_cur[NN];
static __device__ int   g_off[NN + 1];
static __device__ int   g_child[NN];
static __device__ int   g_lvcnt[8];
static __device__ int   g_lvnodes[6 * NN];               // lists for heights 0..5
static __device__ int   g_tA[NN * BB];
static __device__ int   g_tB[NN * BB];
static __device__ unsigned g_barctr;

// ---------------- f32x2 helpers ----------------
__device__ __forceinline__ unsigned long long pack2(float lo, float hi) {
    unsigned long long r;
    asm("mov.b64 %0, {%1, %2};" : "=l"(r) : "r"(__float_as_uint(lo)), "r"(__float_as_uint(hi)));
    return r;
}
__device__ __forceinline__ void unpack2(unsigned long long v, float& lo, float& hi) {
    unsigned int a, b;
    asm("mov.b64 {%0, %1}, %2;" : "=r"(a), "=r"(b) : "l"(v));
    lo = __uint_as_float(a);
    hi = __uint_as_float(b);
}
__device__ __forceinline__ void fma2(unsigned long long& d, unsigned long long a, unsigned long long b) {
    asm("fma.rn.f32x2 %0, %1, %2, %0;" : "+l"(d) : "l"(a), "l"(b));
}

// ---------------- global barrier ----------------
__device__ __forceinline__ void gbar(unsigned target) {
    __syncthreads();
    if (threadIdx.x == 0) {
        __threadfence();
        atomicAdd(&g_barctr, 1u);
        unsigned v;
        do {
            asm volatile("ld.acquire.gpu.u32 %0, [%1];" : "=r"(v) : "l"(&g_barctr) : "memory");
        } while (v < target);
    }
    __syncthreads();
}

// ---------------- setup: fuse + tables + zeroing (1 block) ----------------
__global__ void k_setup(const float* lw1, const float* lb1, const float* lw2, const float* lb2,
                        const float* fw1, const float* fb1, const float* fw2, const float* fb2,
                        const float* tw, const float* tb,
                        const float* emb, const float* node_w, const float* node_b) {
    __shared__ float u[32];
    int t = threadIdx.x;
    for (int i = t; i < NN; i += 1024) { g_cnt[i] = 0; g_cur[i] = 0; }
    if (t < 8) g_lvcnt[t] = 0;
    if (t == 0) g_barctr = 0u;
    int i = t >> 5, j = t & 31;
    float s = 0.f;
    for (int k = 0; k < 32; k++) s += lw1[i * 32 + k] * lw2[k * 32 + j];
    g_Wl[t] = s;
    if (t < 32) {
        float bsum = lb2[t];
        for (int k = 0; k < 32; k++) bsum += lb1[k] * lw2[k * 32 + t];
        g_bl[t] = bsum;
        float uu = 0.f;
        for (int q = 0; q < 32; q++) uu += fw2[t * 32 + q] * tw[q];
        u[t] = uu;
    }
    __syncthreads();
    if (t < 32) {
        float vv = 0.f;
        for (int k = 0; k < 32; k++) vv += fw1[t * 32 + k] * u[k];
        g_v[t] = vv;
    }
    if (t == 0) {
        float ss = tb[0];
        for (int k = 0; k < 32; k++) ss += fb1[k] * u[k];
        for (int q = 0; q < 32; q++) ss += fb2[q] * tw[q];
        g_s = ss;
    }
    __syncthreads();
    for (int idx = t; idx < VOC * 32; idx += 1024) {
        int v = idx >> 5, jj = idx & 31;
        float la = g_bl[jj], lb = 0.f, pa = node_b[jj], pb = 0.f;
        for (int e = 0; e < 16; e++) {
            float ev = emb[v * 16 + e];
            la += ev * g_Wl[e * 32 + jj];
            lb += ev * g_Wl[(16 + e) * 32 + jj];
            pa += ev * node_w[e * 32 + jj];
            pb += ev * node_w[(16 + e) * 32 + jj];
        }
        g_La[idx] = la;
        g_Lb[idx] = lb;
        g_Pa[idx] = pa;
        g_Pb[idx] = pb;
    }
}

// ---------------- the mega kernel ----------------
__global__ void __launch_bounds__(THR, 5) k_mega(
    const int* __restrict__ kind, const int* __restrict__ height,
    const int* __restrict__ parent,
    const int* __restrict__ tok_a, const int* __restrict__ tok_b,
    const int* __restrict__ ptr_time,
    const float* __restrict__ first_notes, const float* __restrict__ lstm,
    const float* __restrict__ node_w,
    const float* __restrict__ ptr_w, const float* __restrict__ ptr_b,
    float* __restrict__ out)
{
    __shared__ float lssh[32 * 68];
    __shared__ float pwT[32 * 68];
    __shared__ int tileb[32][33];
    __shared__ int sA[128];

    const int t = threadIdx.x, bid = blockIdx.x;
    const int wid = t >> 5, lane = t & 31;
    const int jj = lane & 15, half = lane >> 4;

    // W columns in registers: W2[k] = (node_w[32+k][2jj], node_w[32+k][2jj+1])
    unsigned long long W2[32];
    #pragma unroll
    for (int k = 0; k < 32; k++) {
        float2 w = *(const float2*)(node_w + (32 + k) * 32 + 2 * jj);
        W2[k] = pack2(w.x, w.y);
    }

    // ---- level worker ----
    auto do_level = [&](int lvl, int s, int gw, int nw) {
        int cnt = g_lvcnt[lvl];
        int nunits = cnt * 64;
        const int* list = g_lvnodes + lvl * NN;
        for (int u = gw; u < nunits; u += nw) {
            int node = list[u >> 6];
            int bp = u & 63;
            int b = s * 128 + bp * 2 + half;
            int ta = g_tA[node * BB + b];
            int tb = g_tB[node * BB + b];
            float csx = 0.f, csy = 0.f;
            int c0 = g_off[node], c1 = g_off[node + 1];
            for (int ci = c0; ci < c1; ci++) {
                int c = g_child[ci];
                float2 v = *(const float2*)(g_hf + ((size_t)c * BB + b) * 32 + 2 * jj);
                csx += v.x; csy += v.y;
            }
            float2 pa = *(const float2*)(g_Pa + ta * 32 + 2 * jj);
            float2 pb = *(const float2*)(g_Pb + tb * 32 + 2 * jj);
            unsigned long long oA = pack2(pa.x + pb.x, pa.y + pb.y);
            unsigned long long oB = pack2(0.f, 0.f);
            #pragma unroll
            for (int kk = 0; kk < 16; kk++) {
                float lo = __shfl_sync(0xffffffffu, csx, kk, 16);
                float hi = __shfl_sync(0xffffffffu, csy, kk, 16);
                fma2(oA, pack2(lo, lo), W2[2 * kk]);
                fma2(oB, pack2(hi, hi), W2[2 * kk + 1]);
            }
            float a0, a1, b0f, b1f;
            unpack2(oA, a0, a1);
            unpack2(oB, b0f, b1f);
            float2 r;
            r.x = fmaxf(a0 + b0f, 0.f);
            r.y = fmaxf(a1 + b1f, 0.f);
            *(float2*)(g_hf + ((size_t)node * BB + b) * 32 + 2 * jj) = r;
        }
    };

    // ---- leaf worker ----
    auto do_leaf = [&](int s, int gw, int nw) {
        int cnt = g_lvcnt[0];
        int nunits = cnt * 64;
        const int* list = g_lvnodes;
        for (int u = gw; u < nunits; u += nw) {
            int node = list[u >> 6];
            int bp = u & 63;
            int b = s * 128 + bp * 2 + half;
            int kd = kind[node];
            float2 r;
            if (kd == 0) {
                int ta = g_tA[node * BB + b];
                int tb = g_tB[node * BB + b];
                float2 x = *(const float2*)(g_La + ta * 32 + 2 * jj);
                float2 y = *(const float2*)(g_Lb + tb * 32 + 2 * jj);
                r.x = x.x + y.x; r.y = x.y + y.y;
            } else {
                int tm = ptr_time[(size_t)b * NN + node];
                float2 x = *(const float2*)(g_F + b * 32 + 2 * jj);
                float2 y = *(const float2*)(g_Lt + ((size_t)b * TT + tm) * 32 + 2 * jj);
                r.x = x.x + y.x; r.y = x.y + y.y;
            }
            *(float2*)(g_hf + ((size_t)node * BB + b) * 32 + 2 * jj) = r;
        }
    };

    // ---- root partial sum (blocks 0..63) ----
    auto do_F1 = [&](int s) {
        int gw2 = bid * 4 + wid;             // 0..255
        int bp = gw2 & 63, cstride = gw2 >> 6;
        int b = s * 128 + bp * 2 + half;
        float csx = 0.f, csy = 0.f;
        int c0 = g_off[0], c1 = g_off[1];
        for (int ci = c0 + cstride; ci < c1; ci += 4) {
            int c = g_child[ci];
            float2 v = *(const float2*)(g_hf + ((size_t)c * BB + b) * 32 + 2 * jj);
            csx += v.x; csy += v.y;
        }
        g_p2[(cstride * BB + b) * 16 + jj] = make_float2(csx, csy);
    };

    // ---- root finish (block 0) ----
    auto do_F23 = [&](int s) {
        float2 v2 = *(const float2*)(g_v + 2 * jj);
        for (int u = wid; u < 64; u += 4) {
            int b = s * 128 + u * 2 + half;
            float csx = 0.f, csy = 0.f;
            #pragma unroll
            for (int q = 0; q < 4; q++) {
                float2 p = g_p2[(q * BB + b) * 16 + jj];
                csx += p.x; csy += p.y;
            }
            int ta = g_tA[b];
            int tb = g_tB[b];
            float2 pa = *(const float2*)(g_Pa + ta * 32 + 2 * jj);
            float2 pb = *(const float2*)(g_Pb + tb * 32 + 2 * jj);
            unsigned long long oA = pack2(pa.x + pb.x, pa.y + pb.y);
            unsigned long long oB = pack2(0.f, 0.f);
            #pragma unroll
            for (int kk = 0; kk < 16; kk++) {
                float lo = __shfl_sync(0xffffffffu, csx, kk, 16);
                float hi = __shfl_sync(0xffffffffu, csy, kk, 16);
                fma2(oA, pack2(lo, lo), W2[2 * kk]);
                fma2(oB, pack2(hi, hi), W2[2 * kk + 1]);
            }
            float a0, a1, b0f, b1f;
            unpack2(oA, a0, a1);
            unpack2(oB, b0f, b1f);
            float rx = fmaxf(a0 + b0f, 0.f), ry = fmaxf(a1 + b1f, 0.f);
            float d = rx * v2.x + ry * v2.y;
            #pragma unroll
            for (int off = 8; off; off >>= 1) d += __shfl_xor_sync(0xffffffffu, d, off, 16);
            if (jj == 0) out[b] = d + g_s;
        }
    };

    // ================= Phase A =================
    if (bid < 512) {
        // transpose tok_a / tok_b : 2048 tiles of 32x32
        for (int ti = bid; ti < 2048; ti += 512) {
            int arr = ti >> 10;
            int tile = ti & 1023;
            int pt = tile >> 3, bt = tile & 7;
            const int* src = arr ? tok_b : tok_a;
            int* dst = arr ? g_tB : g_tA;
            for (int r = wid; r < 32; r += 4)
                tileb[r][lane] = src[(size_t)(bt * 32 + r) * NN + pt * 32 + lane];
            __syncthreads();
            for (int r = wid; r < 32; r += 4)
                dst[(size_t)(pt * 32 + r) * BB + bt * 32 + lane] = tileb[lane][r];
            __syncthreads();
        }
    } else if (bid < 704) {
        // Lt: 32768 rows x 64 @ 64x32 in groups of 32 rows
        for (int i = t; i < 2048; i += THR)
            pwT[(i & 31) * 68 + (i >> 5)] = ptr_w[2048 + i];
        for (int g = bid - 512; g < 1024; g += 192) {
            __syncthreads();
            size_t base = (size_t)g * 32 * 64;
            for (int i = t; i < 2048; i += THR)
                lssh[(i >> 6) * 68 + (i & 63)] = lstm[base + i];
            __syncthreads();
            float sacc[8];
            #pragma unroll
            for (int r = 0; r < 8; r++) sacc[r] = 0.f;
            #pragma unroll
            for (int k4 = 0; k4 < 64; k4 += 4) {
                float4 wv = *(const float4*)(pwT + lane * 68 + k4);
                #pragma unroll
                for (int r = 0; r < 8; r++) {
                    float4 lv = *(const float4*)(lssh + (wid * 8 + r) * 68 + k4);
                    sacc[r] += lv.x * wv.x + lv.y * wv.y + lv.z * wv.z + lv.w * wv.w;
                }
            }
            int row0 = g * 32 + wid * 8;
            #pragma unroll
            for (int r = 0; r < 8; r++)
                g_Lt[(size_t)(row0 + r) * 32 + lane] = sacc[r];
        }
    } else if (bid < 736) {
        int c = (bid - 704) * THR + t;
        if (c >= 1 && c < NN) atomicAdd(&g_cnt[parent[c]], 1);
        if (c < NN) {
            int h = height[c];
            if (h < 6) {
                int i = atomicAdd(&g_lvcnt[h], 1);
                g_lvnodes[h * NN + i] = c;
            }
        }
    } else {
        for (int idx = (bid - 736) * THR + t; idx < BB * 32; idx += 4 * THR) {
            int b = idx >> 5, j = idx & 31;
            float s = ptr_b[j];
            for (int k = 0; k < 64; k++) s += first_notes[b * 64 + k] * ptr_w[k * 32 + j];
            g_F[idx] = s;
        }
    }
    gbar(GRID * 1);

    // ================= Phase B: scan | leaf s0 =================
    if (bid == 0) {
        int base = t * 32;
        int run = 0;
        for (int r = 0; r < 32; r++) run += g_cnt[base + r];
        sA[t] = run;
        __syncthreads();
        for (int off = 1; off < 128; off <<= 1) {
            int v = (t >= off) ? sA[t - off] : 0;
            __syncthreads();
            sA[t] += v;
            __syncthreads();
        }
        int excl = sA[t] - run;
        for (int r = 0; r < 32; r++) { g_off[base + r] = excl; excl += g_cnt[base + r]; }
        if (t == 127) g_off[NN] = sA[127];
    } else {
        do_leaf(0, (bid - 1) * 4 + wid, 739 * 4);
    }
    gbar(GRID * 2);

    // ================= Phase C: fill | leaf s1 =================
    if (bid < 32) {
        int c = bid * THR + t;
        if (c >= 1 && c < NN) {
            int p = parent[c];
            int pos = atomicAdd(&g_cur[p], 1);
            g_child[g_off[p] + pos] = c;
        }
    } else {
        do_leaf(1, (bid - 32) * 4 + wid, 708 * 4);
    }
    gbar(GRID * 3);

    // ================= Levels 1..5 slice 0 =================
    for (int lvl = 1; lvl <= 5; lvl++) {
        do_level(lvl, 0, bid * 4 + wid, GRID * 4);
        gbar(GRID * (3 + lvl));
    }

    // ================= Phase E: F1 s0 | level1 s1 =================
    if (bid < 64) do_F1(0);
    else do_level(1, 1, (bid - 64) * 4 + wid, 676 * 4);
    gbar(GRID * 9);

    // ================= Phase F: F23 s0 | level2 s1 =================
    if (bid == 0) do_F23(0);
    else do_level(2, 1, (bid - 1) * 4 + wid, 739 * 4);
    gbar(GRID * 10);

    // ================= Levels 3..5 slice 1 =================
    do_level(3, 1, bid * 4 + wid, GRID * 4);
    gbar(GRID * 11);
    do_level(4, 1, bid * 4 + wid, GRID * 4);
    gbar(GRID * 12);
    do_level(5, 1, bid * 4 + wid, GRID * 4);
    gbar(GRID * 13);

    // ================= Phase J: F1 s1 =================
    if (bid < 64) do_F1(1);
    gbar(GRID * 14);

    // ================= Phase K: F23 s1 =================
    if (bid == 0) do_F23(1);
}

// ---------------- launch ----------------
extern "C" void kernel_launch(void* const* d_in, const int* in_sizes, int n_in,
                              void* d_out, int out_size) {
    const int*   kind        = (const int*)d_in[0];
    const int*   height      = (const int*)d_in[1];
    const int*   parent      = (const int*)d_in[2];
    const int*   tok_a       = (const int*)d_in[3];
    const int*   tok_b       = (const int*)d_in[4];
    const int*   ptr_time    = (const int*)d_in[5];
    const float* first_notes = (const float*)d_in[6];
    const float* lstm_out    = (const float*)d_in[7];
    const float* embedding   = (const float*)d_in[8];
    const float* leaf_w1     = (const float*)d_in[9];
    const float* leaf_b1     = (const float*)d_in[10];
    const float* leaf_w2     = (const float*)d_in[11];
    const float* leaf_b2     = (const float*)d_in[12];
    const float* node_w      = (const float*)d_in[13];
    const float* node_b      = (const float*)d_in[14];
    const float* ptr_w       = (const float*)d_in[15];
    const float* ptr_b       = (const float*)d_in[16];
    const float* ff_w1       = (const float*)d_in[17];
    const float* ff_b1       = (const float*)d_in[18];
    const float* ff_w2       = (const float*)d_in[19];
    const float* ff_b2       = (const float*)d_in[20];
    const float* tail_w      = (const float*)d_in[21];
    const float* tail_b      = (const float*)d_in[22];
    float* out = (float*)d_out;

    k_setup<<<1, 1024>>>(leaf_w1, leaf_b1, leaf_w2, leaf_b2,
                         ff_w1, ff_b1, ff_w2, ff_b2, tail_w, tail_b,
                         embedding, node_w, node_b);
    k_mega<<<GRID, THR>>>(kind, height, parent, tok_a, tok_b, ptr_time,
                          first_notes, lstm_out, node_w, ptr_w, ptr_b, out);
}